// round 17
// baseline (speedup 1.0000x reference)
#include <cuda_runtime.h>
#include <cstdint>

#define BB 64
#define SS 512
#define HH 768
#define KK 21
#define FULLMASK 0xffffffffu
#define LOG21 3.0445224377234229f

typedef unsigned long long ull;

// ---------------------------------------------------------------------------
// helpers
// ---------------------------------------------------------------------------
__device__ __forceinline__ void fma2(ull& acc, ull a, ull b) {
    asm("fma.rn.f32x2 %0, %1, %2, %0;" : "+l"(acc) : "l"(a), "l"(b));
}
__device__ __forceinline__ ull add2(ull a, ull b) {
    ull r;
    asm("add.rn.f32x2 %0, %1, %2;" : "=l"(r) : "l"(a), "l"(b));
    return r;
}
__device__ __forceinline__ ull packf2(float lo, float hi) {
    ull r;
    asm("mov.b64 %0, {%1, %2};" : "=l"(r) : "f"(lo), "f"(hi));
    return r;
}
__device__ __forceinline__ float2 unpack2(ull v) {
    float lo, hi;
    asm("mov.b64 {%0,%1}, %2;" : "=f"(lo), "=f"(hi) : "l"(v));
    return make_float2(lo, hi);
}
__device__ __forceinline__ float rcpa(float x) {
    float r;
    asm("rcp.approx.f32 %0, %1;" : "=f"(r) : "f"(x));
    return r;
}
__device__ __forceinline__ void cpa16(void* dst, const void* src) {
    uint32_t d = (uint32_t)__cvta_generic_to_shared(dst);
    asm volatile("cp.async.cg.shared.global [%0], [%1], 16;\n" ::"r"(d), "l"(src));
}

__device__ float4 g_wpack[384 * 11];
__device__ float  g_partial[BB];
__device__ int    g_ctr = 0;
__device__ int    g_packctr = 0;   // monotonic; packed content replay-invariant

// CRF scratch
__device__ float g_res[BB][14][32];   // f1..f7 at [0..6], g2..g8 at [7..13]
__device__ float g_L[BB][14];
__device__ float g_num[BB];
__device__ int   g_seqctr[BB];        // zero-init; combiner resets

// ---------------------------------------------------------------------------
// GEMM v2: hidden via direct LDG.128 (no smem staging; zero reuse anyway).
//   512 blocks x 128 thr; thread (rp = tid>>2, q = tid&3) does rows rp, rp+32
//   and k-quarter q. W via cp.async smem double buffer (5.6KB/chunk).
//   k-quarter combine via 2x shfl_xor. Distributed W pack on blocks 0..63.
// ---------------------------------------------------------------------------
#define GT    128
#define GR    64
#define WCH   352             // 32 k-pairs * 11 col-pairs per 64-k chunk
#define NCH   12

__global__ __launch_bounds__(GT) void gemm_kernel(
    const float* __restrict__ hidden,
    const float* __restrict__ Wg,
    const float* __restrict__ bg,
    float* __restrict__ out) {
    __shared__ float4 wb[2][WCH];
    __shared__ float  shOut[GR * KK];

    const int tid = threadIdx.x;
    const int bx = blockIdx.x;
    const int rp = tid >> 2;      // row 0..31 (second row = rp+32)
    const int q  = tid & 3;       // k-quarter
    const size_t rowBase = (size_t)bx * GR;

    // row pointers (float4 units); q*4 = this thread's 16-float segment
    const float4* hA = (const float4*)(hidden + (rowBase + rp) * HH) + q * 4;
    const float4* hB = hA + 32 * (HH / 4);

    auto LOADW = [&](int c, int buf) {
#pragma unroll
        for (int j = 0; j < 3; j++) {
            int idx = tid + j * GT;
            if (idx < WCH) cpa16(&wb[buf][idx], &g_wpack[c * WCH + idx]);
        }
        asm volatile("cp.async.commit_group;\n");
    };

    // distributed pack: blocks 0..63 each pack 66 float4s, then signal
    if (bx < 64) {
        if (tid < 66) {
            int idx = bx * 66 + tid;
            int p = idx / 11, cc = idx - p * 11;
            int c0 = 2 * cc, c1 = c0 + 1;
            float a = Wg[(2 * p)     * KK + c0];
            float b = Wg[(2 * p + 1) * KK + c0];
            float c = (c1 < KK) ? Wg[(2 * p)     * KK + c1] : 0.f;
            float d = (c1 < KK) ? Wg[(2 * p + 1) * KK + c1] : 0.f;
            g_wpack[idx] = make_float4(a, b, c, d);
        }
        __threadfence();
        __syncthreads();
        if (tid == 0) atomicAdd(&g_packctr, 1);
    }
    {
        volatile int* pc = &g_packctr;
        while (*pc < 64) __nanosleep(32);
    }
    __threadfence();
    LOADW(0, 0);

    ull acc[2 * KK];              // [0..20] row rp, [21..41] row rp+32
#pragma unroll
    for (int i = 0; i < 2 * KK; i++) acc[i] = 0ull;

    for (int c = 0; c < NCH; c++) {
        // hidden for this chunk: 4 float4 per row, direct LDG
        float4 a4[4], b4[4];
#pragma unroll
        for (int j = 0; j < 4; j++) {
            a4[j] = hA[c * (64 / 4) + j];
            b4[j] = hB[c * (64 / 4) + j];
        }

        if (c + 1 < NCH) {
            LOADW(c + 1, (c + 1) & 1);
            asm volatile("cp.async.wait_group 1;\n");
        } else {
            asm volatile("cp.async.wait_group 0;\n");
        }
        __syncthreads();

        const float4* wp = &wb[c & 1][(q * 8) * 11];
#pragma unroll
        for (int p = 0; p < 8; p++) {
            int j = p >> 1, h = p & 1;
            ull h2a = h ? packf2(a4[j].z, a4[j].w) : packf2(a4[j].x, a4[j].y);
            ull h2b = h ? packf2(b4[j].z, b4[j].w) : packf2(b4[j].x, b4[j].y);
            const ulonglong2* wrow = (const ulonglong2*)&wp[p * 11];
#pragma unroll
            for (int cc = 0; cc < 10; cc++) {
                ulonglong2 w2 = wrow[cc];
                fma2(acc[2 * cc],          h2a, w2.x);
                fma2(acc[2 * cc + 1],      h2a, w2.y);
                fma2(acc[KK + 2 * cc],     h2b, w2.x);
                fma2(acc[KK + 2 * cc + 1], h2b, w2.y);
            }
            ulonglong2 w2 = wrow[10];
            fma2(acc[20],      h2a, w2.x);
            fma2(acc[KK + 20], h2b, w2.x);
        }
        __syncthreads();
    }

    // combine k-quarters via shfl (q threads are lane-adjacent), write smem
#pragma unroll
    for (int cc = 0; cc < KK; cc++) {
        float2 fa = unpack2(acc[cc]);
        float2 fb = unpack2(acc[KK + cc]);
        float va = fa.x + fa.y;
        float vb = fb.x + fb.y;
        va += __shfl_xor_sync(FULLMASK, va, 1);
        va += __shfl_xor_sync(FULLMASK, va, 2);
        vb += __shfl_xor_sync(FULLMASK, vb, 1);
        vb += __shfl_xor_sync(FULLMASK, vb, 2);
        if (q == 0) {
            float bias = bg[cc];
            shOut[rp * KK + cc] = va + bias;
            shOut[(32 + rp) * KK + cc] = vb + bias;
        }
    }
    __syncthreads();
    float* outp = out + rowBase * KK;
    for (int i = tid; i < GR * KK; i += GT) outp[i] = shOut[i];
}

// ---------------------------------------------------------------------------
// CRF (identical to R16): rank-1 scan, 8 segments, 2 blocks/batch.
// ---------------------------------------------------------------------------
#define RN 16

__device__ __forceinline__ int seq_len_w(const void* maskraw, int b, int lane) {
    const int* im = (const int*)maskraw;
    bool bytes = (im[0] != 1);
    int len = 0;
    if (!bytes) {
        const int* m = im + b * SS;
        for (int t = lane; t < SS; t += 32) len += (m[t] != 0);
    } else {
        const unsigned char* m = (const unsigned char*)maskraw + b * SS;
        for (int t = lane; t < SS; t += 32) len += (m[t] != 0);
    }
#pragma unroll
    for (int o = 16; o; o >>= 1) len += __shfl_xor_sync(FULLMASK, len, o);
    return len;
}

__device__ __forceinline__ float crf_sstep(float* sb, int rb, const ull* tE2,
                                           float e0, int lane) {
    const ulonglong2* sp = (const ulonglong2*)(sb + rb * 24);
    ulonglong2 q0 = sp[0], q1 = sp[1], q2 = sp[2];
    ulonglong2 q3 = sp[3], q4 = sp[4], q5 = sp[5];
    ull A = 0ull, B = 0ull, C = 0ull;
    fma2(A, q0.x, tE2[0]);  fma2(B, q0.y, tE2[1]);  fma2(C, q1.x, tE2[2]);
    fma2(A, q1.y, tE2[3]);  fma2(B, q2.x, tE2[4]);  fma2(C, q2.y, tE2[5]);
    fma2(A, q3.x, tE2[6]);  fma2(B, q3.y, tE2[7]);  fma2(C, q4.x, tE2[8]);
    fma2(A, q4.y, tE2[9]);  fma2(B, q5.x, tE2[10]); fma2(C, q5.y, tE2[11]);
    A = add2(A, B);
    A = add2(A, C);
    float2 f = unpack2(A);
    float u = (f.x + f.y) * e0;
    if (lane < KK) sb[(rb ^ 1) * 24 + lane] = u;
    __syncwarp();
    return u;
}

__device__ __forceinline__ float crf_run_s(float uinit, float& logC,
                                           const ull* tE2, float* sb,
                                           const float* lg, int jj,
                                           int base, int dir, int n, int lane) {
    if (lane < 24) {
        sb[lane]      = (lane < KK) ? uinit : 0.f;
        sb[24 + lane] = 0.f;
    }
    __syncwarp();
    if (n <= 0) return uinit;

    float u = uinit;
    float ev[RN], evn[RN];
#pragma unroll
    for (int j = 0; j < RN; j++) {
        int idx = (j < n) ? j : n - 1;
        ev[j] = lg[(base + dir * idx) * KK + jj];
    }
    float pend = 1.f, lpend = 0.f;
    int rb = 0;
    int pos = 0;
    while (pos + RN <= n) {
#pragma unroll
        for (int j = 0; j < RN; j++) {
            int idx = pos + RN + j; idx = (idx < n) ? idx : n - 1;
            evn[j] = lg[(base + dir * idx) * KK + jj];
        }
        float e0 = __expf(ev[0]) * pend;
        logC += lpend;
#pragma unroll
        for (int j = 0; j < RN; j++) {
            float e1 = __expf(ev[(j + 1) & (RN - 1)]);
            u = crf_sstep(sb, rb, tE2, e0, lane);
            rb ^= 1;
            e0 = e1;
        }
        float c = sb[rb * 24];
        pend = rcpa(c);
        lpend = __logf(c);
#pragma unroll
        for (int j = 0; j < RN; j++) ev[j] = evn[j];
        pos += RN;
    }
    int tail = n - pos;
    if (tail) {
        float e0 = __expf(ev[0]) * pend;
        logC += lpend;
        for (int j = 0; j < tail; j++) {
            u = crf_sstep(sb, rb, tE2, e0, lane);
            rb ^= 1;
            e0 = __expf(ev[(j + 1) & (RN - 1)]);
        }
    }
    logC += (float)n * LOG21;
    return u;
}

__device__ __forceinline__ float wsum(float v) {
#pragma unroll
    for (int o = 16; o; o >>= 1) v += __shfl_xor_sync(FULLMASK, v, o);
    return v;
}

__global__ __launch_bounds__(256) void crf_kernel(
    const float* __restrict__ logits,
    const int*   __restrict__ labels,
    const void*  __restrict__ maskraw,
    const float* __restrict__ start_t,
    const float* __restrict__ trans,
    const float* __restrict__ end_t,
    float* __restrict__ out_nll) {
    const int b = blockIdx.x;
    const int role = blockIdx.y;
    const int tid = threadIdx.x;
    const int lane = tid & 31;
    const int w = tid >> 5;
    const int jj = (lane < KK) ? lane : KK - 1;

    __shared__ __align__(16) float s_st[8][48];

    const int len = seq_len_w(maskraw, b, lane);
    const int*   lab = labels + b * SS;
    const float* lg  = logits + (size_t)b * SS * KK;

    if (role == 0 && w == 7) {
        float num = 0.f;
        for (int t = lane; t < len; t += 32) {
            int lt = lab[t];
            float e = lg[t * KK + lt];
            num += (t == 0) ? (start_t[lt] + e)
                            : (e + trans[lab[t - 1] * KK + lt]);
        }
        num = wsum(num);
        if (lane == 0) g_num[b] = num + end_t[lab[len - 1]];
    } else if (w < 7) {
        const bool fwd = (role == 0);
        float tE[24];
#pragma unroll
        for (int i = 0; i < KK; i++)
            tE[i] = __expf(fwd ? trans[i * KK + jj] : trans[jj * KK + i])
                    * (1.f / 21.f);
        tE[21] = tE[22] = tE[23] = 0.f;
        ull tE2[12];
#pragma unroll
        for (int i = 0; i < 12; i++) tE2[i] = packf2(tE[2 * i], tE[2 * i + 1]);

        int base, n, dir, slot;
        float uinit = 1.f, logC = 0.f;
        if (fwd) {
            int i = w + 1;
            int qp = ((i - 1) * len) >> 3;
            int qi = (i * len) >> 3;
            base = qp + 1; dir = +1; n = qi - qp;
            slot = i - 1;
            if (i == 1) {
                float a0 = (lane < KK) ? (start_t[lane] + lg[lane]) : -1e30f;
                float m0 = a0;
#pragma unroll
                for (int o = 16; o; o >>= 1)
                    m0 = fmaxf(m0, __shfl_xor_sync(FULLMASK, m0, o));
                uinit = __expf(a0 - m0);
                logC = m0;
            }
        } else {
            int i = w + 2;
            int qp = ((i - 1) * len) >> 3;
            int qi = (i == 8) ? (len - 1) : ((i * len) >> 3);
            base = qi; dir = -1; n = qi - qp;
            slot = i + 5;
            if (i == 8) uinit = __expf(end_t[jj]);
        }

        float u = crf_run_s(uinit, logC, tE2, s_st[w], lg, jj,
                            base, dir, n, lane);
        float c0 = __shfl_sync(FULLMASK, u, 0);
        u = u / c0;
        logC += __logf(c0);
        g_res[b][slot][lane] = (lane < KK) ? u : 0.f;
        if (lane == 0) g_L[b][slot] = logC;
    }

    __syncthreads();
    __shared__ int sOld;
    if (tid == 0) {
        __threadfence();
        sOld = atomicAdd(&g_seqctr[b], 1);
    }
    __syncthreads();
    if (sOld != 1 || w != 0) return;

    __threadfence();
    float acc = g_L[b][13];
#pragma unroll
    for (int i = 0; i < 7; i++) acc += g_L[b][i];
#pragma unroll
    for (int i = 1; i <= 7; i++) {
        float d = wsum(g_res[b][i - 1][lane] * g_res[b][i + 6][lane]);
        acc += __logf(d);
    }
#pragma unroll
    for (int i = 2; i <= 7; i++) {
        float sg = wsum(g_res[b][i + 5][lane]);
        acc -= __logf(sg);
    }
    if (lane == 0) {
        g_partial[b] = acc - g_num[b];
        g_seqctr[b] = 0;
        __threadfence();
        int old = atomicAdd(&g_ctr, 1);
        if (old == BB - 1) {
            __threadfence();
            float tot = 0.f;
            for (int i = 0; i < BB; i++) tot += g_partial[i];
            out_nll[0] = tot;
            g_ctr = 0;
        }
    }
}

// ---------------------------------------------------------------------------
extern "C" void kernel_launch(void* const* d_in, const int* in_sizes, int n_in,
                              void* d_out, int out_size) {
    const float* hidden  = (const float*)d_in[0];
    const float* W       = (const float*)d_in[1];
    const float* b       = (const float*)d_in[2];
    const float* start_t = (const float*)d_in[3];
    const float* trans   = (const float*)d_in[4];
    const float* end_t   = (const float*)d_in[5];
    const int*   labels  = (const int*)d_in[6];
    const void*  mask    = (const void*)d_in[7];

    float* out     = (float*)d_out;
    float* out_nll = out + (out_size - 1);

    gemm_kernel<<<(BB * SS) / GR, GT>>>(hidden, W, b, out);
    crf_kernel<<<dim3(BB, 2), 256>>>(out, labels, mask, start_t, trans, end_t,
                                     out_nll);
}